// round 8
// baseline (speedup 1.0000x reference)
#include <cuda_runtime.h>

#define BB 128
#define HH 256
#define WW 256
#define SHIFT 32
#define HW (HH*WW)      // 65536
#define CHW (3*HW)      // 196608
#define RBLKS 32        // reduce role-units per image
#define BPI 64          // transform role-units per image
#define NC 4            // pipeline chunks
#define QTR (BB/NC)     // 32 images per chunk
#define NBLK (148*6)    // one resident wave (launch_bounds enforces >=6 blk/SM)

__device__ float g_part[BB * RBLKS];
__device__ volatile unsigned g_barcnt;   // zero-init; self-resetting
__device__ volatile unsigned g_bargen;   // monotone generation (relative compare)

// Grid-wide sense-reversal barrier. Valid ONLY because the grid is one
// resident wave (all blocks co-scheduled). Self-resets for graph replay.
__device__ __forceinline__ void gbar() {
    __syncthreads();
    if (threadIdx.x == 0) {
        __threadfence();
        unsigned gen = g_bargen;
        if (atomicAdd((unsigned*)&g_barcnt, 1u) == NBLK - 1) {
            g_barcnt = 0;
            __threadfence();
            g_bargen = gen + 1;
        } else {
            while (g_bargen == gen) __nanosleep(64);
        }
        __threadfence();
    }
    __syncthreads();
}

// ---- reduce role-unit: sum 1/32 of one image, write one partial ----
__device__ __forceinline__ void reduce_role(const float* __restrict__ imgs,
                                            int b, int blk)
{
    const float4* p = (const float4*)(imgs + (size_t)b * CHW);
    const int per_blk = (CHW / 4) / RBLKS;   // 1536 float4
    int base = blk * per_blk;
    float s0 = 0.f, s1 = 0.f;
    #pragma unroll
    for (int i = 0; i < 6; i += 2) {
        float4 va = p[base + i * 256 + threadIdx.x];
        float4 vb = p[base + (i + 1) * 256 + threadIdx.x];
        s0 += (va.x + va.y) + (va.z + va.w);
        s1 += (vb.x + vb.y) + (vb.z + vb.w);
    }
    float s = s0 + s1;
    #pragma unroll
    for (int o = 16; o; o >>= 1) s += __shfl_down_sync(0xffffffffu, s, o);
    __shared__ float ss[8];
    if ((threadIdx.x & 31) == 0) ss[threadIdx.x >> 5] = s;
    __syncthreads();
    if (threadIdx.x < 8) {
        s = ss[threadIdx.x];
        #pragma unroll
        for (int o = 4; o; o >>= 1) s += __shfl_down_sync(0xffu, s, o);
        if (threadIdx.x == 0) g_part[b * RBLKS + blk] = s;
    }
    __syncthreads();   // ss reuse safety across role-units
}

// ---- transform role-unit: one float4 per thread in each of 3 planes ----
__device__ __forceinline__ void transform_role(
    const float* __restrict__ imgs,
    const float* __restrict__ br,  const float* __restrict__ sat,
    const float* __restrict__ con, const int* __restrict__ tx,
    const int* __restrict__ ty,    const int* __restrict__ cx,
    const int* __restrict__ cy,    float* __restrict__ out,
    int b, int blk)
{
    int idx4 = blk * 256 + threadIdx.x;               // float4 index in plane
    int h    = idx4 >> 6;
    int w0   = (idx4 & 63) << 2;

    __shared__ float sM0;
    if (threadIdx.x < 32) {
        float s = g_part[b * RBLKS + threadIdx.x];
        #pragma unroll
        for (int o = 16; o; o >>= 1) s += __shfl_down_sync(0xffffffffu, s, o);
        if (threadIdx.x == 0) sM0 = s * (1.0f / (float)CHW);
    }
    __syncthreads();

    float a  = sat[b] * 2.0f;
    float k  = con[b] + 0.5f;
    float Af = k * a;
    float Bf = k * (1.0f - a);
    float Cf = (1.0f - k) * sM0 + (br[b] - 0.5f);

    int txs = tx[b] - SHIFT;
    int tys = ty[b] - SHIFT;
    int cxv = cx[b], cyv = cy[b];
    int xlo = max(0, cxv - 64), xhi = min(HH - 1, cxv + 63);
    int ylo = max(0, cyv - 64), yhi = min(WW - 1, cyv + 63);

    int  sh       = h + txs;
    bool rowvalid = (sh >= 0) & (sh < HH);
    bool rowcut   = (h >= xlo) & (h <= xhi);
    int  sh_c     = min(max(sh, 0), HH - 1);

    const float* src = imgs + (size_t)b * CHW + (size_t)sh_c * WW;

    float o0[4], o1[4], o2[4];
    #pragma unroll
    for (int j = 0; j < 4; j++) {
        int  w  = w0 + j;
        int  sw = w + tys;
        bool valid = rowvalid & (sw >= 0) & (sw < WW)
                   & !(rowcut & (w >= ylo) & (w <= yhi));
        int sw_c = min(max(sw, 0), WW - 1);
        if (valid) {
            float v0 = __ldcs(src + sw_c);
            float v1 = __ldcs(src + HW + sw_c);
            float v2 = __ldcs(src + 2 * HW + sw_c);
            float m  = (v0 + v1 + v2) * (1.0f / 3.0f);
            float bm = fmaf(Bf, m, Cf);
            o0[j] = fmaf(Af, v0, bm);
            o1[j] = fmaf(Af, v1, bm);
            o2[j] = fmaf(Af, v2, bm);
        } else {
            o0[j] = 0.f; o1[j] = 0.f; o2[j] = 0.f;
        }
    }

    float* dst = out + (size_t)b * CHW + (size_t)h * WW + w0;
    __stcs((float4*)(dst),          make_float4(o0[0], o0[1], o0[2], o0[3]));
    __stcs((float4*)(dst + HW),     make_float4(o1[0], o1[1], o1[2], o1[3]));
    __stcs((float4*)(dst + 2 * HW), make_float4(o2[0], o2[1], o2[2], o2[3]));
    __syncthreads();   // sM0 reuse safety across role-units
}

// Persistent one-wave kernel: internal software pipeline over NC chunks.
__global__ void __launch_bounds__(256, 6) augment_persistent(
    const float* __restrict__ imgs,
    const float* __restrict__ br,  const float* __restrict__ sat,
    const float* __restrict__ con, const int* __restrict__ tx,
    const int* __restrict__ ty,    const int* __restrict__ cx,
    const int* __restrict__ cy,    float* __restrict__ out)
{
    const int RBC = QTR * RBLKS;   // 1024 reduce units per chunk
    const int TBC = QTR * BPI;     // 2048 transform units per chunk

    // prologue: reduce chunk 0
    for (int vb = blockIdx.x; vb < RBC; vb += NBLK)
        reduce_role(imgs, 0 * QTR + vb / RBLKS, vb % RBLKS);
    gbar();

    #pragma unroll 1
    for (int c = 0; c < NC; c++) {
        if (c + 1 < NC)
            for (int vb = blockIdx.x; vb < RBC; vb += NBLK)
                reduce_role(imgs, (c + 1) * QTR + vb / RBLKS, vb % RBLKS);
        for (int vb = blockIdx.x; vb < TBC; vb += NBLK)
            transform_role(imgs, br, sat, con, tx, ty, cx, cy, out,
                           c * QTR + vb / BPI, vb % BPI);
        if (c + 1 < NC) gbar();
    }
}

extern "C" void kernel_launch(void* const* d_in, const int* in_sizes, int n_in,
                              void* d_out, int out_size)
{
    const float* imgs = (const float*)d_in[0];
    const float* br   = (const float*)d_in[1];
    const float* sat  = (const float*)d_in[2];
    const float* con  = (const float*)d_in[3];
    const int*   tx   = (const int*)d_in[4];
    const int*   ty   = (const int*)d_in[5];
    const int*   cx   = (const int*)d_in[6];
    const int*   cy   = (const int*)d_in[7];
    float*       out  = (float*)d_out;

    augment_persistent<<<NBLK, 256>>>(imgs, br, sat, con, tx, ty, cx, cy, out);
}

// round 9
// speedup vs baseline: 1.1182x; 1.1182x over previous
#include <cuda_runtime.h>

#define BB 128
#define HH 256
#define WW 256
#define SHIFT 32
#define HW (HH*WW)      // 65536
#define CHW (3*HW)      // 196608
#define RBLKS 16        // reduce role-units per image (12-deep LDG.128 each)
#define BPI 64          // transform role-units per image
#define HALF (BB/2)     // 64 images per chunk

__device__ float g_part[BB * RBLKS];

// ---- reduce role: one block sums 1/16 of one image, writes one partial ----
// 3072 float4 per block, 12 per thread, front-batched for MLP=12.
__device__ __forceinline__ void reduce_role(const float* __restrict__ imgs,
                                            int b, int blk)
{
    const float4* p = (const float4*)(imgs + (size_t)b * CHW)
                    + blk * ((CHW / 4) / RBLKS) + threadIdx.x;
    float4 v[12];
    #pragma unroll
    for (int i = 0; i < 12; i++) v[i] = p[i * 256];
    float s0 = 0.f, s1 = 0.f, s2 = 0.f, s3 = 0.f;
    #pragma unroll
    for (int i = 0; i < 12; i += 4) {
        s0 += (v[i].x   + v[i].y)   + (v[i].z   + v[i].w);
        s1 += (v[i+1].x + v[i+1].y) + (v[i+1].z + v[i+1].w);
        s2 += (v[i+2].x + v[i+2].y) + (v[i+2].z + v[i+2].w);
        s3 += (v[i+3].x + v[i+3].y) + (v[i+3].z + v[i+3].w);
    }
    float s = (s0 + s1) + (s2 + s3);
    #pragma unroll
    for (int o = 16; o; o >>= 1) s += __shfl_down_sync(0xffffffffu, s, o);
    __shared__ float ss[8];
    if ((threadIdx.x & 31) == 0) ss[threadIdx.x >> 5] = s;
    __syncthreads();
    if (threadIdx.x < 8) {
        s = ss[threadIdx.x];
        #pragma unroll
        for (int o = 4; o; o >>= 1) s += __shfl_down_sync(0xffu, s, o);
        if (threadIdx.x == 0) g_part[b * RBLKS + blk] = s;
    }
}

// ---- transform role: one float4 per thread in each of 3 planes ----
__device__ __forceinline__ void transform_role(
    const float* __restrict__ imgs,
    const float* __restrict__ br,  const float* __restrict__ sat,
    const float* __restrict__ con, const int* __restrict__ tx,
    const int* __restrict__ ty,    const int* __restrict__ cx,
    const int* __restrict__ cy,    float* __restrict__ out,
    int b, int blk)
{
    int idx4 = blk * 256 + threadIdx.x;               // float4 index in plane
    int h    = idx4 >> 6;
    int w0   = (idx4 & 63) << 2;

    // Half a warp sums this image's 16 partials (L2-broadcast hits).
    __shared__ float sM0;
    if (threadIdx.x < 16) {
        float s = g_part[b * RBLKS + threadIdx.x];
        #pragma unroll
        for (int o = 8; o; o >>= 1) s += __shfl_down_sync(0xffffu, s, o);
        if (threadIdx.x == 0) sM0 = s * (1.0f / (float)CHW);
    }
    __syncthreads();

    float a  = sat[b] * 2.0f;
    float k  = con[b] + 0.5f;
    float Af = k * a;
    float Bf = k * (1.0f - a);
    float Cf = (1.0f - k) * sM0 + (br[b] - 0.5f);

    int txs = tx[b] - SHIFT;
    int tys = ty[b] - SHIFT;
    int cxv = cx[b], cyv = cy[b];
    int xlo = max(0, cxv - 64), xhi = min(HH - 1, cxv + 63);
    int ylo = max(0, cyv - 64), yhi = min(WW - 1, cyv + 63);

    int  sh       = h + txs;
    bool rowvalid = (sh >= 0) & (sh < HH);
    bool rowcut   = (h >= xlo) & (h <= xhi);
    int  sh_c     = min(max(sh, 0), HH - 1);

    const float* src = imgs + (size_t)b * CHW + (size_t)sh_c * WW;

    float o0[4], o1[4], o2[4];
    #pragma unroll
    for (int j = 0; j < 4; j++) {
        int  w  = w0 + j;
        int  sw = w + tys;
        bool valid = rowvalid & (sw >= 0) & (sw < WW)
                   & !(rowcut & (w >= ylo) & (w <= yhi));
        int sw_c = min(max(sw, 0), WW - 1);
        if (valid) {
            float v0 = __ldcs(src + sw_c);            // last-use reads
            float v1 = __ldcs(src + HW + sw_c);
            float v2 = __ldcs(src + 2 * HW + sw_c);
            float m  = (v0 + v1 + v2) * (1.0f / 3.0f);
            float bm = fmaf(Bf, m, Cf);
            o0[j] = fmaf(Af, v0, bm);
            o1[j] = fmaf(Af, v1, bm);
            o2[j] = fmaf(Af, v2, bm);
        } else {
            o0[j] = 0.f; o1[j] = 0.f; o2[j] = 0.f;
        }
    }

    float* dst = out + (size_t)b * CHW + (size_t)h * WW + w0;
    __stcs((float4*)(dst),          make_float4(o0[0], o0[1], o0[2], o0[3]));
    __stcs((float4*)(dst + HW),     make_float4(o1[0], o1[1], o1[2], o1[3]));
    __stcs((float4*)(dst + 2 * HW), make_float4(o2[0], o2[1], o2[2], o2[3]));
}

// Mixed kernel. FIRST nred*RBLKS blocks reduce images [rbase,...) — these have
// NO dependency on the previous kernel and run as soon as PDL dispatches them.
// The remaining transform blocks call cudaGridDependencySynchronize() to wait
// for the previous kernel's partial sums before transforming [tbase,...).
__global__ void __launch_bounds__(256) fused_kernel(
    const float* __restrict__ imgs,
    const float* __restrict__ br,  const float* __restrict__ sat,
    const float* __restrict__ con, const int* __restrict__ tx,
    const int* __restrict__ ty,    const int* __restrict__ cx,
    const int* __restrict__ cy,    float* __restrict__ out,
    int tbase, int rbase, int nred)
{
    int nredblk = nred * RBLKS;
    if ((int)blockIdx.x < nredblk) {
        reduce_role(imgs, rbase + blockIdx.x / RBLKS, blockIdx.x % RBLKS);
    } else {
        cudaGridDependencySynchronize();   // wait: upstream partials complete
        int tix = blockIdx.x - nredblk;
        transform_role(imgs, br, sat, con, tx, ty, cx, cy, out,
                       tbase + tix / BPI, tix % BPI);
    }
}

extern "C" void kernel_launch(void* const* d_in, const int* in_sizes, int n_in,
                              void* d_out, int out_size)
{
    const float* imgs = (const float*)d_in[0];
    const float* br   = (const float*)d_in[1];
    const float* sat  = (const float*)d_in[2];
    const float* con  = (const float*)d_in[3];
    const int*   tx   = (const int*)d_in[4];
    const int*   ty   = (const int*)d_in[5];
    const int*   cx   = (const int*)d_in[6];
    const int*   cy   = (const int*)d_in[7];
    float*       out  = (float*)d_out;

    const int RB = HALF * RBLKS;   // 1024 reduce blocks per half
    const int TB = HALF * BPI;     // 4096 transform blocks per half

    cudaLaunchAttribute attr[1];
    attr[0].id = cudaLaunchAttributeProgrammaticStreamSerialization;
    attr[0].val.programmaticStreamSerializationAllowed = 1;

    // K0: reduce half 0 (plain launch)
    fused_kernel<<<RB, 256>>>(imgs, br, sat, con, tx, ty, cx, cy, out,
                              /*tbase*/0, /*rbase*/0, /*nred*/HALF);

    // K1: reduce half 1 (independent, overlaps K0 tail) + transform half 0
    {
        cudaLaunchConfig_t cfg = {};
        cfg.gridDim = dim3(RB + TB); cfg.blockDim = dim3(256);
        cfg.attrs = attr; cfg.numAttrs = 1;
        cudaLaunchKernelEx(&cfg, fused_kernel, imgs, br, sat, con, tx, ty, cx, cy, out,
                           /*tbase*/0, /*rbase*/HALF, /*nred*/HALF);
    }
    // K2: transform half 1 (starts during K1 drain; gridsync gates data use)
    {
        cudaLaunchConfig_t cfg = {};
        cfg.gridDim = dim3(TB); cfg.blockDim = dim3(256);
        cfg.attrs = attr; cfg.numAttrs = 1;
        cudaLaunchKernelEx(&cfg, fused_kernel, imgs, br, sat, con, tx, ty, cx, cy, out,
                           /*tbase*/HALF, /*rbase*/0, /*nred*/0);
    }
}